// round 1
// baseline (speedup 1.0000x reference)
#include <cuda_runtime.h>

#define VOCAB   32000
#define EMBED   256
#define HIDDEN  512
#define BATCH   32
#define MAXLEN  64
#define GO_ID   2
#define EOS_ID  3

// d_out layout (float32, tuple order flattened):
//   w_pro [64,32,32000] | w_o [64,32] | emb_seq [64,32,256] | length [32]
#define WPRO_OFF 0ull
#define WO_OFF   65536000ull
#define EMB_OFF  65538048ull
#define LEN_OFF  66062336ull

// ---------------- persistent scratch (device globals; no allocs) ------------
__device__ float g_h[2][BATCH][HIDDEN];
__device__ float g_hT[HIDDEN][BATCH];      // transposed h for K2 staging
__device__ float g_x[BATCH][EMBED];        // current input embedding
__device__ float g_sumExp[BATCH];
__device__ unsigned long long g_argPack[BATCH];
__device__ int   g_flag[BATCH];
__device__ int   g_len[BATCH];

// ---------------- helpers ---------------------------------------------------
__device__ __forceinline__ unsigned long long f2pack(float lo, float hi) {
    unsigned long long r;
    asm("mov.b64 %0, {%1, %2};" : "=l"(r) : "f"(lo), "f"(hi));
    return r;
}
__device__ __forceinline__ unsigned long long fma2(unsigned long long a,
                                                   unsigned long long b,
                                                   unsigned long long c) {
    unsigned long long d;
    asm("fma.rn.f32x2 %0, %1, %2, %3;" : "=l"(d) : "l"(a), "l"(b), "l"(c));
    return d;
}
__device__ __forceinline__ float f2sum(unsigned long long p) {
    float lo, hi;
    asm("mov.b64 {%0, %1}, %2;" : "=f"(lo), "=f"(hi) : "l"(p));
    return lo + hi;
}
__device__ __forceinline__ unsigned ford(float f) {
    unsigned u = __float_as_uint(f);
    return (u & 0x80000000u) ? ~u : (u | 0x80000000u);
}

// ---------------- K0: init --------------------------------------------------
__global__ void k0_init(const float* __restrict__ emb, const float* __restrict__ h0) {
    int tid = blockIdx.x * blockDim.x + threadIdx.x;  // 64*256 = 16384
    if (tid < BATCH * HIDDEN) ((float*)g_h)[tid] = h0[tid];  // g_h[0]
    if (tid < BATCH * EMBED) {
        int b = tid / EMBED, e = tid % EMBED;
        g_x[b][e] = emb[GO_ID * EMBED + e];
    }
    if (tid < BATCH) { g_flag[tid] = 0; g_len[tid] = 0; }
}

// ---------------- K1: GRU cell ----------------------------------------------
// warp per (b, 4 consecutive j). 512 blocks x 256 threads = 4096 warps.
__global__ __launch_bounds__(256) void k1_gru(
    const float* __restrict__ Wih, const float* __restrict__ bih,
    const float* __restrict__ Whh, const float* __restrict__ bhh, int t) {
    if (blockIdx.x == 0 && threadIdx.x < BATCH) {
        g_sumExp[threadIdx.x] = 0.f;
        g_argPack[threadIdx.x] = 0ull;
    }
    int w    = blockIdx.x * 8 + (threadIdx.x >> 5);
    int lane = threadIdx.x & 31;
    int b    = w >> 7;            // 128 j-quads per batch row
    int j0   = (w & 127) * 4;
    const float* hcur = g_h[t & 1][b];
    const float* x    = g_x[b];

    float4 xv[2], hv[4];
#pragma unroll
    for (int i = 0; i < 2; i++) xv[i] = ((const float4*)x)[lane * 2 + i];
#pragma unroll
    for (int i = 0; i < 4; i++) hv[i] = ((const float4*)hcur)[lane * 4 + i];

#pragma unroll
    for (int jj = 0; jj < 4; jj++) {
        int j = j0 + jj;
        float s[6];
#pragma unroll
        for (int g = 0; g < 3; g++) {
            const float4* wr = (const float4*)(Wih + (size_t)(g * HIDDEN + j) * EMBED);
            float a = 0.f;
#pragma unroll
            for (int i = 0; i < 2; i++) {
                float4 wv = wr[lane * 2 + i];
                a += wv.x * ((i == 0) ? xv[0].x : xv[1].x)
                   + wv.y * ((i == 0) ? xv[0].y : xv[1].y)
                   + wv.z * ((i == 0) ? xv[0].z : xv[1].z)
                   + wv.w * ((i == 0) ? xv[0].w : xv[1].w);
            }
            s[g] = a;
        }
#pragma unroll
        for (int g = 0; g < 3; g++) {
            const float4* wr = (const float4*)(Whh + (size_t)(g * HIDDEN + j) * HIDDEN);
            float a = 0.f;
#pragma unroll
            for (int i = 0; i < 4; i++) {
                float4 wv = wr[lane * 4 + i];
                a += wv.x * hv[i].x + wv.y * hv[i].y + wv.z * hv[i].z + wv.w * hv[i].w;
            }
            s[3 + g] = a;
        }
#pragma unroll
        for (int g = 0; g < 6; g++)
#pragma unroll
            for (int off = 16; off; off >>= 1)
                s[g] += __shfl_xor_sync(0xFFFFFFFFu, s[g], off);
        if (lane == 0) {
            float ir = s[0] + bih[j], iz = s[1] + bih[HIDDEN + j], in_ = s[2] + bih[2 * HIDDEN + j];
            float hr = s[3] + bhh[j], hz = s[4] + bhh[HIDDEN + j], hn  = s[5] + bhh[2 * HIDDEN + j];
            float r = 1.f / (1.f + __expf(-(ir + hr)));
            float z = 1.f / (1.f + __expf(-(iz + hz)));
            float n = tanhf(in_ + r * hn);
            float hnew = (1.f - z) * n + z * hcur[j];
            g_h[(t + 1) & 1][b][j] = hnew;
            g_hT[j][b] = hnew;
        }
    }
}

// ---------------- K2: logits GEMM + exp + partial softmax/argmax -------------
// 125 blocks x 256 cols. 256 threads: bg=tid&7 (4 b each), cg=tid>>3 (8 c each).
// Thread tile 4b x 8c, accumulators k-parity-paired in f32x2.
#define CT 256
#define KT 64
__global__ __launch_bounds__(256) void k2_logits(
    const float* __restrict__ Wout, const float* __restrict__ bout,
    float* __restrict__ out, int t) {
    extern __shared__ float4 sm4[];
    float4* ws4 = sm4;                 // [256 rows][16 f4] xor-swizzled
    float4* hs4 = sm4 + CT * 16;       // [512][8]  == g_hT as float4
    float* sb = (float*)(sm4 + CT * 16 + HIDDEN * 8);
    unsigned long long* sa = (unsigned long long*)(sb + 32);

    int tid = threadIdx.x;
    int bg = tid & 7, cg = tid >> 3;
    if (tid < 32) { sb[tid] = 0.f; sa[tid] = 0ull; }

    const float4* hT4 = (const float4*)g_hT;
#pragma unroll
    for (int r = 0; r < 16; r++) hs4[r * 256 + tid] = hT4[r * 256 + tid];

    int C0 = blockIdx.x * CT;
    unsigned long long acc[4][8];
#pragma unroll
    for (int i = 0; i < 4; i++)
#pragma unroll
        for (int j = 0; j < 8; j++) acc[i][j] = 0ull;

    const float4* W4 = (const float4*)Wout;
    int swz = cg & 7;

    for (int kc = 0; kc < 8; kc++) {
        int ktf4 = kc * (KT / 4);
        __syncthreads();
#pragma unroll
        for (int r = 0; r < 16; r++) {
            int g = r * 256 + tid;
            int c = g >> 4, k4 = g & 15;
            ws4[c * 16 + (k4 ^ ((c >> 3) & 7))] = W4[(size_t)(C0 + c) * 128 + ktf4 + k4];
        }
        __syncthreads();
#pragma unroll
        for (int k4 = 0; k4 < 16; k4++) {
            float4 wv[8];
#pragma unroll
            for (int j = 0; j < 8; j++)
                wv[j] = ws4[(8 * cg + j) * 16 + (k4 ^ swz)];
            int kr = kc * KT + k4 * 4;
            float4 hA = hs4[(kr + 0) * 8 + bg];
            float4 hB = hs4[(kr + 1) * 8 + bg];
            float4 hC = hs4[(kr + 2) * 8 + bg];
            float4 hD = hs4[(kr + 3) * 8 + bg];
            unsigned long long p01[4], p23[4];
            p01[0] = f2pack(hA.x, hB.x); p01[1] = f2pack(hA.y, hB.y);
            p01[2] = f2pack(hA.z, hB.z); p01[3] = f2pack(hA.w, hB.w);
            p23[0] = f2pack(hC.x, hD.x); p23[1] = f2pack(hC.y, hD.y);
            p23[2] = f2pack(hC.z, hD.z); p23[3] = f2pack(hC.w, hD.w);
#pragma unroll
            for (int j = 0; j < 8; j++) {
                unsigned long long w01 = f2pack(wv[j].x, wv[j].y);
                unsigned long long w23 = f2pack(wv[j].z, wv[j].w);
#pragma unroll
                for (int i = 0; i < 4; i++) {
                    acc[i][j] = fma2(p01[i], w01, acc[i][j]);
                    acc[i][j] = fma2(p23[i], w23, acc[i][j]);
                }
            }
        }
    }

    // epilogue
    int cbase = C0 + 8 * cg;
#pragma unroll
    for (int i = 0; i < 4; i++) {
        int b = 4 * bg + i;
        float vals[8];
#pragma unroll
        for (int j = 0; j < 8; j++) vals[j] = f2sum(acc[i][j]) + __ldg(bout + cbase + j);

        // local argmax (strict > keeps first occurrence), skip cols < 2
        float best = -3.0e38f; int bc = -1;
#pragma unroll
        for (int j = 0; j < 8; j++) {
            int c = cbase + j;
            if (c >= 2 && vals[j] > best) { best = vals[j]; bc = c; }
        }
        if (bc >= 0) {
            unsigned long long pk = ((unsigned long long)ford(best) << 32)
                                  | (unsigned long long)(0x7FFFFFFFu - (unsigned)bc);
            atomicMax(&sa[b], pk);
        }
        float e[8]; float es = 0.f;
#pragma unroll
        for (int j = 0; j < 8; j++) { e[j] = __expf(vals[j]); es += e[j]; }
        atomicAdd(&sb[b], es);

        size_t base = WPRO_OFF + (size_t)t * BATCH * VOCAB + (size_t)b * VOCAB + cbase;
        float4* po = (float4*)(out + base);
        po[0] = make_float4(e[0], e[1], e[2], e[3]);
        po[1] = make_float4(e[4], e[5], e[6], e[7]);
    }
    __syncthreads();
    if (tid < 32) {
        atomicAdd(&g_sumExp[tid], sb[tid]);
        atomicMax(&g_argPack[tid], sa[tid]);
    }
}

// ---------------- K3: normalize softmax + token/emb/flag logic ---------------
__global__ __launch_bounds__(256) void k3_final(
    const float* __restrict__ emb, float* __restrict__ out, int t) {
    if (blockIdx.x < 512) {
        int b = blockIdx.x >> 4, ch = blockIdx.x & 15;
        int c0 = ch * 2048 + threadIdx.x * 8;
        if (c0 < VOCAB) {
            float inv = 1.0f / g_sumExp[b];
            size_t base = WPRO_OFF + (size_t)t * BATCH * VOCAB + (size_t)b * VOCAB + c0;
            float4* p = (float4*)(out + base);
            float4 a = p[0], q = p[1];
            a.x *= inv; a.y *= inv; a.z *= inv; a.w *= inv;
            q.x *= inv; q.y *= inv; q.z *= inv; q.w *= inv;
            p[0] = a; p[1] = q;
        }
    } else {
        __shared__ int stok[BATCH];
        __shared__ int salive[BATCH];
        int tid = threadIdx.x;
        if (tid < BATCH) {
            unsigned long long pk = g_argPack[tid];
            int tok = (int)(0x7FFFFFFFu - (unsigned)(pk & 0xFFFFFFFFull));
            int eos = g_flag[tid];
            int alive = eos ? 0 : 1;
            g_flag[tid] = eos | (tok == EOS_ID);
            int ln = g_len[tid] + alive;
            g_len[tid] = ln;
            out[WO_OFF + (size_t)t * BATCH + tid] = (float)(alive ? tok : 0);
            if (t == MAXLEN - 1) out[LEN_OFF + tid] = (float)ln;
            stok[tid] = tok;
            salive[tid] = alive;
        }
        __syncthreads();
        // embeddings: 32*256 floats = 2048 f4, 8 per thread
#pragma unroll
        for (int r = 0; r < 8; r++) {
            int g = r * 256 + tid;
            int b = g >> 6;
            int e4 = g & 63;
            float4 v = ((const float4*)(emb + (size_t)stok[b] * EMBED))[e4];
            ((float4*)g_x)[g] = v;                      // next-step input (un-zeroed)
            float4 z = salive[b] ? v : make_float4(0.f, 0.f, 0.f, 0.f);
            ((float4*)(out + EMB_OFF + (size_t)t * BATCH * EMBED))[g] = z;
        }
    }
}

// ---------------- launch -----------------------------------------------------
extern "C" void kernel_launch(void* const* d_in, const int* in_sizes, int n_in,
                              void* d_out, int out_size) {
    const float* emb  = (const float*)d_in[0];
    const float* Wih  = (const float*)d_in[1];
    const float* bih  = (const float*)d_in[2];
    const float* Whh  = (const float*)d_in[3];
    const float* bhh  = (const float*)d_in[4];
    const float* Wout = (const float*)d_in[5];
    const float* bout = (const float*)d_in[6];
    const float* h0   = (const float*)d_in[7];
    float* out = (float*)d_out;

    size_t smem = (size_t)(CT * 16 + HIDDEN * 8) * sizeof(float4)
                + 32 * sizeof(float) + 32 * sizeof(unsigned long long);
    cudaFuncSetAttribute(k2_logits, cudaFuncAttributeMaxDynamicSharedMemorySize, (int)smem);

    k0_init<<<64, 256>>>(emb, h0);
    for (int t = 0; t < MAXLEN; t++) {
        k1_gru<<<512, 256>>>(Wih, bih, Whh, bhh, t);
        k2_logits<<<125, 256, smem>>>(Wout, bout, out, t);
        k3_final<<<513, 256>>>(emb, out, t);
    }
}

// round 7
// speedup vs baseline: 1.5880x; 1.5880x over previous
#include <cuda_runtime.h>
#include <cuda_bf16.h>
#include <cstdint>

#define VOCAB   32000
#define EMBED   256
#define HIDDEN  512
#define BATCH   32
#define MAXLEN  64
#define GO_ID   2
#define EOS_ID  3

// d_out layout (float32): w_pro [64,32,32000] | w_o [64,32] | emb_seq [64,32,256] | length [32]
#define WPRO_OFF 0ull
#define WO_OFF   65536000ull
#define EMB_OFF  65538048ull
#define LEN_OFF  66062336ull

// ---------------- persistent scratch ----------------------------------------
__device__ float g_h[2][BATCH][HIDDEN];
__device__ float g_x[BATCH][EMBED];
__device__ float g_sumExp[BATCH];
__device__ unsigned long long g_argPack[BATCH];
__device__ int   g_flag[BATCH];
__device__ int   g_len[BATCH];
// bf16 split operands: A rows [c] = [W_hi(512) | W_lo(512)]
__device__ __align__(16) __nv_bfloat16 g_wb[(size_t)VOCAB * 1024];
// B rows [n] : n<32 -> [h_hi|h_hi], n>=32 -> [h_lo|h_lo]
__device__ __align__(16) __nv_bfloat16 g_hb[64][1024];

// ---------------- helpers ----------------------------------------------------
__device__ __forceinline__ unsigned smem_u32(const void* p) {
    unsigned a;
    asm("{ .reg .u64 t; cvta.to.shared.u64 t, %1; cvt.u32.u64 %0, t; }" : "=r"(a) : "l"(p));
    return a;
}
__device__ __forceinline__ unsigned ford(float f) {
    unsigned u = __float_as_uint(f);
    return (u & 0x80000000u) ? ~u : (u | 0x80000000u);
}
#define SWZ(row, off) ((off) ^ (((row) & 7) << 4))

__device__ __forceinline__ void ldm4(unsigned& r0, unsigned& r1, unsigned& r2, unsigned& r3,
                                     unsigned addr) {
    asm volatile("ldmatrix.sync.aligned.m8n8.x4.shared.b16 {%0,%1,%2,%3}, [%4];"
                 : "=r"(r0), "=r"(r1), "=r"(r2), "=r"(r3) : "r"(addr));
}
__device__ __forceinline__ void mma16816(float* c, const unsigned* a, unsigned b0, unsigned b1) {
    asm volatile(
        "mma.sync.aligned.m16n8k16.row.col.f32.bf16.bf16.f32 "
        "{%0,%1,%2,%3}, {%4,%5,%6,%7}, {%8,%9}, {%0,%1,%2,%3};"
        : "+f"(c[0]), "+f"(c[1]), "+f"(c[2]), "+f"(c[3])
        : "r"(a[0]), "r"(a[1]), "r"(a[2]), "r"(a[3]), "r"(b0), "r"(b1));
}

// ---------------- K0: init ---------------------------------------------------
__global__ void k0_init(const float* __restrict__ emb, const float* __restrict__ h0) {
    int tid = blockIdx.x * blockDim.x + threadIdx.x;
    if (tid < BATCH * HIDDEN) ((float*)g_h)[tid] = h0[tid];
    if (tid < BATCH * EMBED) {
        int b = tid / EMBED, e = tid % EMBED;
        g_x[b][e] = emb[GO_ID * EMBED + e];
    }
    if (tid < BATCH) { g_flag[tid] = 0; g_len[tid] = 0; }
}

// ---------------- Kc: W_out -> bf16 hi/lo split (once) -----------------------
__global__ __launch_bounds__(256) void kc_conv(const float* __restrict__ Wout) {
    int idx4 = blockIdx.x * 256 + threadIdx.x;
    if (idx4 >= VOCAB * HIDDEN / 4) return;
    float4 w = ((const float4*)Wout)[idx4];
    int row = idx4 >> 7;
    int k0  = (idx4 & 127) * 4;
    __nv_bfloat16 h0_ = __float2bfloat16(w.x), h1 = __float2bfloat16(w.y);
    __nv_bfloat16 h2 = __float2bfloat16(w.z), h3 = __float2bfloat16(w.w);
    __nv_bfloat16 l0 = __float2bfloat16(w.x - __bfloat162float(h0_));
    __nv_bfloat16 l1 = __float2bfloat16(w.y - __bfloat162float(h1));
    __nv_bfloat16 l2 = __float2bfloat16(w.z - __bfloat162float(h2));
    __nv_bfloat16 l3 = __float2bfloat16(w.w - __bfloat162float(h3));
    __nv_bfloat16* base = g_wb + (size_t)row * 1024;
    *(__nv_bfloat162*)(base + k0)           = __nv_bfloat162(h0_, h1);
    *(__nv_bfloat162*)(base + k0 + 2)       = __nv_bfloat162(h2, h3);
    *(__nv_bfloat162*)(base + 512 + k0)     = __nv_bfloat162(l0, l1);
    *(__nv_bfloat162*)(base + 512 + k0 + 2) = __nv_bfloat162(l2, l3);
}

// ---------------- K1: GRU cell -----------------------------------------------
__global__ __launch_bounds__(256) void k1_gru(
    const float* __restrict__ Wih, const float* __restrict__ bih,
    const float* __restrict__ Whh, const float* __restrict__ bhh, int t) {
    if (blockIdx.x == 0 && threadIdx.x < BATCH) {
        g_sumExp[threadIdx.x] = 0.f;
        g_argPack[threadIdx.x] = 0ull;
    }
    int w    = blockIdx.x * 8 + (threadIdx.x >> 5);
    int lane = threadIdx.x & 31;
    int b    = w >> 7;
    int j0   = (w & 127) * 4;
    const float* hcur = g_h[t & 1][b];
    const float* x    = g_x[b];

    float4 xv[2], hv[4];
#pragma unroll
    for (int i = 0; i < 2; i++) xv[i] = ((const float4*)x)[lane * 2 + i];
#pragma unroll
    for (int i = 0; i < 4; i++) hv[i] = ((const float4*)hcur)[lane * 4 + i];

#pragma unroll
    for (int jj = 0; jj < 4; jj++) {
        int j = j0 + jj;
        float s[6];
#pragma unroll
        for (int g = 0; g < 3; g++) {
            const float4* wr = (const float4*)(Wih + (size_t)(g * HIDDEN + j) * EMBED);
            float a = 0.f;
#pragma unroll
            for (int i = 0; i < 2; i++) {
                float4 wv = wr[lane * 2 + i];
                a += wv.x * ((i == 0) ? xv[0].x : xv[1].x)
                   + wv.y * ((i == 0) ? xv[0].y : xv[1].y)
                   + wv.z * ((i == 0) ? xv[0].z : xv[1].z)
                   + wv.w * ((i == 0) ? xv[0].w : xv[1].w);
            }
            s[g] = a;
        }
#pragma unroll
        for (int g = 0; g < 3; g++) {
            const float4* wr = (const float4*)(Whh + (size_t)(g * HIDDEN + j) * HIDDEN);
            float a = 0.f;
#pragma unroll
            for (int i = 0; i < 4; i++) {
                float4 wv = wr[lane * 4 + i];
                a += wv.x * hv[i].x + wv.y * hv[i].y + wv.z * hv[i].z + wv.w * hv[i].w;
            }
            s[3 + g] = a;
        }
#pragma unroll
        for (int g = 0; g < 6; g++)
#pragma unroll
            for (int off = 16; off; off >>= 1)
                s[g] += __shfl_xor_sync(0xFFFFFFFFu, s[g], off);
        if (lane == 0) {
            float ir = s[0] + bih[j], iz = s[1] + bih[HIDDEN + j], in_ = s[2] + bih[2 * HIDDEN + j];
            float hr = s[3] + bhh[j], hz = s[4] + bhh[HIDDEN + j], hn  = s[5] + bhh[2 * HIDDEN + j];
            float r = 1.f / (1.f + __expf(-(ir + hr)));
            float z = 1.f / (1.f + __expf(-(iz + hz)));
            float n = tanhf(in_ + r * hn);
            float hnew = (1.f - z) * n + z * hcur[j];
            g_h[(t + 1) & 1][b][j] = hnew;
            __nv_bfloat16 hh = __float2bfloat16(hnew);
            __nv_bfloat16 hl = __float2bfloat16(hnew - __bfloat162float(hh));
            g_hb[b][j]            = hh;
            g_hb[b][512 + j]      = hh;
            g_hb[32 + b][j]       = hl;
            g_hb[32 + b][512 + j] = hl;
        }
    }
}

// ---------------- K2: mma.sync logits GEMM + softmax/argmax partials ---------
// 125 CTAs x 256 thr. Per CTA: 256 vocab rows x N=64, K=1024 in 16 chunks of 64.
// Double-buffered cp.async stages: A [256][64]bf16 swizzled + B [64][64]bf16.
#define CT 256
#define NCHUNK 16
#define STAGE_BYTES 40960
#define B_OFF 32768
#define CS_STRIDE 65

__global__ __launch_bounds__(256, 1)
void k2m(const float* __restrict__ bout, float* __restrict__ out, int t) {
    extern __shared__ char smem[];
    __shared__ float sb[32];
    __shared__ unsigned long long sa[32];

    unsigned smb = smem_u32(smem);
    int tid = threadIdx.x, wid = tid >> 5, lane = tid & 31;
    if (tid < 32) { sb[tid] = 0.f; sa[tid] = 0ull; }
    int C0 = blockIdx.x * CT;

    float acc[2][8][4];
#pragma unroll
    for (int i = 0; i < 2; i++)
#pragma unroll
        for (int j = 0; j < 8; j++)
#pragma unroll
            for (int q = 0; q < 4; q++) acc[i][j][q] = 0.f;

    // per-lane ldmatrix invariants
    int a_r = lane & 15, a_kh = (lane >> 4) << 4;                 // A: row, k-half bytes
    int b_n = (lane & 7) | ((lane >> 4) << 3);                    // B: n within j-pair
    int b_kh = ((lane >> 3) & 1) << 4;

    const char* wsrc = (const char*)g_wb + (size_t)C0 * 2048;
    const char* hsrc = (const char*)g_hb;

    // -------- producer macro: load chunk cc into stage s ---------------------
#define LOAD_CHUNK(cc, s)                                                        \
    {                                                                            \
        unsigned stb = smb + (s) * STAGE_BYTES;                                  \
        int kb = (cc) * 128;                                                     \
        _Pragma("unroll")                                                        \
        for (int i = 0; i < 10; i++) {                                           \
            int op = tid + 256 * i;                                              \
            if (op < 2560) {                                                     \
                const char* src; unsigned dst;                                   \
                if (op < 2048) {                                                 \
                    int m = op >> 3, q = (op & 7) << 4;                          \
                    src = wsrc + (size_t)m * 2048 + kb + q;                      \
                    dst = stb + m * 128 + SWZ(m, q);                             \
                } else {                                                         \
                    int o = op - 2048;                                           \
                    int n = o >> 3, q = (o & 7) << 4;                            \
                    src = hsrc + (size_t)n * 2048 + kb + q;                      \
                    dst = stb + B_OFF + n * 128 + SWZ(n, q);                     \
                }                                                                \
                asm volatile("cp.async.cg.shared.global [%0], [%1], 16;"         \
                             :: "r"(dst), "l"(src) : "memory");                  \
            }                                                                    \
        }                                                                        \
        asm volatile("cp.async.commit_group;" ::: "memory");                     \
    }

    LOAD_CHUNK(0, 0)

    for (int cc = 0; cc < NCHUNK; cc++) {
        int s = cc & 1;
        asm volatile("cp.async.wait_group 0;" ::: "memory");
        __syncthreads();
        if (cc + 1 < NCHUNK) LOAD_CHUNK(cc + 1, (s ^ 1))

        unsigned As = smb + s * STAGE_BYTES;
        unsigned Bs = As + B_OFF;
#pragma unroll
        for (int ks = 0; ks < 4; ks++) {
            int ko = ks << 5;  // 32 bytes per k16 step
            unsigned a[2][4], bb[4][4];
#pragma unroll
            for (int i = 0; i < 2; i++) {
                int m = wid * 32 + i * 16 + a_r;
                ldm4(a[i][0], a[i][1], a[i][2], a[i][3],
                     As + m * 128 + SWZ(m, ko + a_kh));
            }
#pragma unroll
            for (int jp = 0; jp < 4; jp++) {
                int n = jp * 16 + b_n;
                ldm4(bb[jp][0], bb[jp][1], bb[jp][2], bb[jp][3],
                     Bs + n * 128 + SWZ(n, ko + b_kh));
            }
#pragma unroll
            for (int i = 0; i < 2; i++)
#pragma unroll
                for (int j = 0; j < 8; j++) {
                    const unsigned* bj = bb[j >> 1];
                    mma16816(acc[i][j], a[i], bj[(j & 1) * 2], bj[(j & 1) * 2 + 1]);
                }
        }
    }

    // -------- write accumulators to SMEM (stride-65 float rows) --------------
    __syncthreads();
    float* Cs = (float*)smem;
    {
        int qr = lane >> 2, qc = (lane & 3) * 2;
#pragma unroll
        for (int i = 0; i < 2; i++) {
            int r0 = wid * 32 + i * 16 + qr;
#pragma unroll
            for (int j = 0; j < 8; j++) {
                int n = j * 8 + qc;
                Cs[r0 * CS_STRIDE + n]           = acc[i][j][0];
                Cs[r0 * CS_STRIDE + n + 1]       = acc[i][j][1];
                Cs[(r0 + 8) * CS_STRIDE + n]     = acc[i][j][2];
                Cs[(r0 + 8) * CS_STRIDE + n + 1] = acc[i][j][3];
            }
        }
    }
    __syncthreads();

    // -------- epilogue: warp w -> vocab rows [w*32, w*32+32), lane = row -----
    {
        int cl = wid * 32 + lane;
        int c  = C0 + cl;
        float bv = __ldg(bout + c);
        float lg[32], ex[32];
#pragma unroll
        for (int b = 0; b < 32; b++)
            lg[b] = Cs[cl * CS_STRIDE + b] + Cs[cl * CS_STRIDE + b + 32] + bv;
#pragma unroll
        for (int b = 0; b < 32; b++) ex[b] = __expf(lg[b]);

        size_t obase = WPRO_OFF + (size_t)t * BATCH * VOCAB + (size_t)c;
#pragma unroll
        for (int b = 0; b < 32; b++) out[obase + (size_t)b * VOCAB] = ex[b];

        // warp all-reduce sum in place on ex
#pragma unroll
        for (int off = 16; off; off >>= 1)
#pragma unroll
            for (int b = 0; b < 32; b++)
                ex[b] += __shfl_xor_sync(0xFFFFFFFFu, ex[b], off);
        atomicAdd(&sb[lane], ex[lane]);

        float mx[32];
#pragma unroll
        for (int b = 0; b < 32; b++) mx[b] = (c >= 2) ? lg[b] : -3.0e38f;
#pragma unroll
        for (int off = 16; off; off >>= 1)
#pragma unroll
            for (int b = 0; b < 32; b++)
                mx[b] = fmaxf(mx[b], __shfl_xor_sync(0xFFFFFFFFu, mx[b], off));
#pragma unroll
        for (int b = 0; b < 32; b++) {
            if (c >= 2 && lg[b] == mx[b]) {
                unsigned long long pk = ((unsigned long long)ford(lg[b]) << 32)
                                      | (unsigned long long)(0x7FFFFFFFu - (unsigned)c);
                atomicMax(&sa[b], pk);
            }
        }
    }
    __syncthreads();
    if (tid < 32) {
        atomicAdd(&g_sumExp[tid], sb[tid]);
        atomicMax(&g_argPack[tid], sa[tid]);
    }
#undef LOAD_CHUNK
}

// ---------------- K3: normalize softmax + token/emb/flag logic ---------------
// blocks 0..999: normalize (one independent float4 per thread, 256K threads)
// block 1000:    token/eos/emb logic
__global__ __launch_bounds__(256) void k3_final(
    const float* __restrict__ emb, float* __restrict__ out, int t) {
    if (blockIdx.x < 1000) {
        int g = blockIdx.x * 256 + threadIdx.x;     // 0..255999 float4 ids
        int b = g / 8000;                            // 8000 f4 per batch row
        int c4 = g - b * 8000;
        float inv = 1.0f / g_sumExp[b];
        size_t base = WPRO_OFF + (size_t)t * BATCH * VOCAB + (size_t)b * VOCAB + (size_t)c4 * 4;
        float4* p = (float4*)(out + base);
        float4 a = *p;
        a.x *= inv; a.y *= inv; a.z *= inv; a.w *= inv;
        *p = a;
    } else {
        __shared__ int stok[BATCH];
        __shared__ int salive[BATCH];
        int tid = threadIdx.x;
        if (tid < BATCH) {
            unsigned long long pk = g_argPack[tid];
            int tok = (int)(0x7FFFFFFFu - (unsigned)(pk & 0xFFFFFFFFull));
            int eos = g_flag[tid];
            int alive = eos ? 0 : 1;
            g_flag[tid] = eos | (tok == EOS_ID);
            int ln = g_len[tid] + alive;
            g_len[tid] = ln;
            out[WO_OFF + (size_t)t * BATCH + tid] = (float)(alive ? tok : 0);
            if (t == MAXLEN - 1) out[LEN_OFF + tid] = (float)ln;
            stok[tid] = tok;
            salive[tid] = alive;
        }
        __syncthreads();
#pragma unroll
        for (int r = 0; r < 8; r++) {
            int g = r * 256 + tid;
            int b = g >> 6;
            int e4 = g & 63;
            float4 v = ((const float4*)(emb + (size_t)stok[b] * EMBED))[e4];
            ((float4*)g_x)[g] = v;
            float4 z = salive[b] ? v : make_float4(0.f, 0.f, 0.f, 0.f);
            ((float4*)(out + EMB_OFF + (size_t)t * BATCH * EMBED))[g] = z;
        }
    }
}

// ---------------- launch -----------------------------------------------------
extern "C" void kernel_launch(void* const* d_in, const int* in_sizes, int n_in,
                              void* d_out, int out_size) {
    const float* emb  = (const float*)d_in[0];
    const float* Wih  = (const float*)d_in[1];
    const float* bih  = (const float*)d_in[2];
    const float* Whh  = (const float*)d_in[3];
    const float* bhh  = (const float*)d_in[4];
    const float* Wout = (const float*)d_in[5];
    const float* bout = (const float*)d_in[6];
    const float* h0   = (const float*)d_in[7];
    float* out = (float*)d_out;

    // smem: max(2 stages = 81920, Cs = 256*65*4 = 66560) -> 81920
    cudaFuncSetAttribute(k2m, cudaFuncAttributeMaxDynamicSharedMemorySize, 2 * STAGE_BYTES);

    k0_init<<<64, 256>>>(emb, h0);
    kc_conv<<<VOCAB * HIDDEN / 4 / 256, 256>>>(Wout);
    for (int t = 0; t < MAXLEN; t++) {
        k1_gru<<<512, 256>>>(Wih, bih, Whh, bhh, t);
        k2m<<<125, 256, 2 * STAGE_BYTES>>>(bout, out, t);
        k3_final<<<1001, 256>>>(emb, out, t);
    }
}